// round 2
// baseline (speedup 1.0000x reference)
#include <cuda_runtime.h>
#include <stdint.h>
#include <math.h>

typedef unsigned long long u64;

#define DD  20
#define RPT 4            // rows per thread (2 packed f32x2 pairs)
#define TPB 128
#define NBLK 304         // 152 SMs x 2 CTAs (persistent grid)

// ---------------- device scratch (no allocs allowed) ----------------
__device__ float  g_M1[DD*DD];   // M1[k][m] = sum_j W[j,k]*Wi[j,m]
__device__ float  g_c1[DD];      // c1[m]    = sum_j b[j]*Wi[j,m] + 1
__device__ float  g_Wt[DD*DD];   // Wt[m][n] = W[n,m]  (for h3 = h2 @ W^T)
__device__ double g_psum[NBLK];
__device__ double g_pabs[NBLK];

// ---------------- packed f32x2 helpers ----------------
__device__ __forceinline__ u64 fma2(u64 a, u64 b, u64 c) {
    u64 d;
    asm("fma.rn.f32x2 %0, %1, %2, %3;" : "=l"(d) : "l"(a), "l"(b), "l"(c));
    return d;
}
__device__ __forceinline__ u64 add2(u64 a, u64 b) {
    u64 d;
    asm("add.rn.f32x2 %0, %1, %2;" : "=l"(d) : "l"(a), "l"(b));
    return d;
}
__device__ __forceinline__ u64 pack2(float lo, float hi) {
    u64 d;
    asm("mov.b64 %0, {%1, %2};" : "=l"(d) : "f"(lo), "f"(hi));
    return d;
}
__device__ __forceinline__ float lo2(u64 v) { return __uint_as_float((unsigned)v); }
__device__ __forceinline__ float hi2(u64 v) { return __uint_as_float((unsigned)(v >> 32)); }
__device__ __forceinline__ u64 relu2(u64 v) {
    return pack2(fmaxf(lo2(v), 0.0f), fmaxf(hi2(v), 0.0f));
}

// ---------------- setup: fold first two matmuls, transpose W (parallel fp32) ----
__global__ void setup_kernel(const float* __restrict__ W,
                             const float* __restrict__ b,
                             const float* __restrict__ Wi) {
    __shared__ float sW[DD*DD], sWi[DD*DD];
    int t = threadIdx.x;
    if (t < DD*DD) { sW[t] = W[t]; sWi[t] = Wi[t]; }
    __syncthreads();
    if (t < DD*DD) {
        int k = t / DD, m = t % DD;
        float acc = 0.0f;
        #pragma unroll
        for (int j = 0; j < DD; j++)
            acc = fmaf(sW[j*DD + k], sWi[j*DD + m], acc);
        g_M1[t] = acc;
        g_Wt[t] = sW[m*DD + k];       // Wt[m][n] = W[n][m], t = m*DD+n -> W[n*DD+m]... see below
    }
    if (t < DD) {
        float acc = 1.0f;
        #pragma unroll
        for (int j = 0; j < DD; j++)
            acc = fmaf(b[j], sWi[j*DD + t], acc);
        g_c1[t] = acc;
    }
}
// NOTE on g_Wt: with t = m*DD + n we want Wt[m][n] = W[n][m] = sW[n*DD + m].
// Above, k = t/DD = m and m_ = t%DD = n, so sW[m_*DD + k] = sW[n*DD + m]. Correct.

// ---------------- main: 4 rows/thread, f32x2 packed, persistent grid ----------
__global__ void __launch_bounds__(TPB, 2)
main_kernel(const float* __restrict__ X, const float* __restrict__ b,
            long long nrows) {
    // duplicated (w,w) 64-bit pairs; 16B-aligned so LDS.128 grabs 2 at a time
    __shared__ __align__(16) u64 sM1[DD*DD];
    __shared__ __align__(16) u64 sWt[DD*DD];
    __shared__ u64 sc1[DD];
    __shared__ u64 sb[DD];

    int t = threadIdx.x;
    for (int i = t; i < DD*DD; i += TPB) {
        float v = g_M1[i]; sM1[i] = pack2(v, v);
        float w = g_Wt[i]; sWt[i] = pack2(w, w);
    }
    if (t < DD) {
        float v = g_c1[t]; sc1[t] = pack2(v, v);
        float w = b[t];    sb[t]  = pack2(w, w);
    }
    __syncthreads();

    long long ngroups  = nrows / RPT;
    long long tid      = (long long)blockIdx.x * TPB + t;
    long long nthreads = (long long)gridDim.x * TPB;

    u64 psum = 0ull, pabs = 0ull;   // packed (0.0f, 0.0f)

    for (long long g = tid; g < ngroups; g += nthreads) {
        const float4* p = (const float4*)(X + g * (long long)(RPT * DD));

        // ---- rows 0,1 -> x0 (pack immediately, keep float regs transient) ----
        u64 x0[DD], x1[DD];
        {
            float4 q[5], r[5];
            #pragma unroll
            for (int i = 0; i < 5; i++) q[i] = p[i];
            #pragma unroll
            for (int i = 0; i < 5; i++) r[i] = p[5 + i];
            #pragma unroll
            for (int i = 0; i < 5; i++) {
                x0[4*i+0] = pack2(q[i].x, r[i].x);
                x0[4*i+1] = pack2(q[i].y, r[i].y);
                x0[4*i+2] = pack2(q[i].z, r[i].z);
                x0[4*i+3] = pack2(q[i].w, r[i].w);
            }
        }
        {
            float4 q[5], r[5];
            #pragma unroll
            for (int i = 0; i < 5; i++) q[i] = p[10 + i];
            #pragma unroll
            for (int i = 0; i < 5; i++) r[i] = p[15 + i];
            #pragma unroll
            for (int i = 0; i < 5; i++) {
                x1[4*i+0] = pack2(q[i].x, r[i].x);
                x1[4*i+1] = pack2(q[i].y, r[i].y);
                x1[4*i+2] = pack2(q[i].z, r[i].z);
                x1[4*i+3] = pack2(q[i].w, r[i].w);
            }
        }

        // ---- h = relu(X @ M1 + c1) : one LDS.128 feeds 4 FFMA2 ----
        u64 h0[DD], h1[DD];
        #pragma unroll
        for (int m = 0; m < DD; m++) { h0[m] = sc1[m]; h1[m] = sc1[m]; }
        #pragma unroll
        for (int k = 0; k < DD; k++) {
            #pragma unroll
            for (int m = 0; m < DD; m += 2) {
                ulonglong2 w = *(const ulonglong2*)&sM1[k*DD + m];
                h0[m]   = fma2(x0[k], w.x, h0[m]);
                h0[m+1] = fma2(x0[k], w.y, h0[m+1]);
                h1[m]   = fma2(x1[k], w.x, h1[m]);
                h1[m+1] = fma2(x1[k], w.y, h1[m+1]);
            }
        }
        #pragma unroll
        for (int m = 0; m < DD; m++) { h0[m] = relu2(h0[m]); h1[m] = relu2(h1[m]); }
        // x0/x1 dead here -> registers recycled for o0/o1

        // ---- h3 = h @ W^T + b (same structure: output-array accumulators) ----
        u64 o0[DD], o1[DD];
        #pragma unroll
        for (int n = 0; n < DD; n++) { o0[n] = sb[n]; o1[n] = sb[n]; }
        #pragma unroll
        for (int m = 0; m < DD; m++) {
            #pragma unroll
            for (int n = 0; n < DD; n += 2) {
                ulonglong2 w = *(const ulonglong2*)&sWt[m*DD + n];
                o0[n]   = fma2(h0[m], w.x, o0[n]);
                o0[n+1] = fma2(h0[m], w.y, o0[n+1]);
                o1[n]   = fma2(h1[m], w.x, o1[n]);
                o1[n+1] = fma2(h1[m], w.y, o1[n+1]);
            }
        }

        // ---- accumulate sum and |.|-sum ----
        #pragma unroll
        for (int n = 0; n < DD; n++) {
            psum = add2(psum, add2(o0[n], o1[n]));
            pabs = add2(pabs, add2(o0[n] & 0x7FFFFFFF7FFFFFFFull,
                                   o1[n] & 0x7FFFFFFF7FFFFFFFull));
        }
    }

    // ---- scalar tail (nrows % 4), one thread only ----
    if (blockIdx.x == 0 && t == 0) {
        for (long long r = ngroups * RPT; r < nrows; r++) {
            float hs[DD];
            for (int m = 0; m < DD; m++) {
                float acc = lo2(sc1[m]);
                for (int k = 0; k < DD; k++)
                    acc = fmaf(X[r*DD + k], lo2(sM1[k*DD + m]), acc);
                hs[m] = fmaxf(acc, 0.0f);
            }
            for (int n = 0; n < DD; n++) {
                float acc = lo2(sb[n]);
                for (int m = 0; m < DD; m++)
                    acc = fmaf(hs[m], lo2(sWt[m*DD + n]), acc);
                psum = add2(psum, pack2(acc, 0.0f));
                pabs = add2(pabs, pack2(fabsf(acc), 0.0f));
            }
        }
    }

    // ---- reduce: warp shuffle -> shared -> per-block partial ----
    float ts = lo2(psum) + hi2(psum);
    float ta = lo2(pabs) + hi2(pabs);
    #pragma unroll
    for (int o = 16; o > 0; o >>= 1) {
        ts += __shfl_down_sync(0xFFFFFFFFu, ts, o);
        ta += __shfl_down_sync(0xFFFFFFFFu, ta, o);
    }
    __shared__ double rs[TPB/32], ra[TPB/32];
    if ((t & 31) == 0) { rs[t >> 5] = (double)ts; ra[t >> 5] = (double)ta; }
    __syncthreads();
    if (t == 0) {
        double S = 0.0, A = 0.0;
        #pragma unroll
        for (int i = 0; i < TPB/32; i++) { S += rs[i]; A += ra[i]; }
        g_psum[blockIdx.x] = S;
        g_pabs[blockIdx.x] = A;
    }
}

// ---------------- finalize: reduce partials, halving count, write scalar ----
__global__ void final_kernel(float* __restrict__ out, int nb) {
    __shared__ double ss[512], sa[512];
    int t = threadIdx.x;
    double S = 0.0, A = 0.0;
    for (int i = t; i < nb; i += 512) { S += g_psum[i]; A += g_pabs[i]; }
    ss[t] = S; sa[t] = A;
    __syncthreads();
    for (int o = 256; o > 0; o >>= 1) {
        if (t < o) { ss[t] += ss[t + o]; sa[t] += sa[t + o]; }
        __syncthreads();
    }
    if (t == 0) {
        float s = (float)sa[0];
        int k = 0;
        while (s > 1.0f && k < 300) { s *= 0.5f; k++; }
        out[0] = (float)ldexp(ss[0], -k);   // sum(h) * 2^-k, exact scale
    }
}

// ---------------- launch ----------------
extern "C" void kernel_launch(void* const* d_in, const int* in_sizes, int n_in,
                              void* d_out, int out_size) {
    const float* X  = (const float*)d_in[0];
    const float* W  = (const float*)d_in[1];
    const float* b  = (const float*)d_in[2];
    const float* Wi = (const float*)d_in[3];

    long long nrows = (long long)in_sizes[0] / DD;

    setup_kernel<<<1, 512>>>(W, b, Wi);
    main_kernel<<<NBLK, TPB>>>(X, b, nrows);
    final_kernel<<<1, 512>>>((float*)d_out, NBLK);
}

// round 3
// speedup vs baseline: 9.6700x; 9.6700x over previous
#include <cuda_runtime.h>
#include <stdint.h>
#include <math.h>

typedef unsigned long long u64;

#define DD  20
#define RPT 4            // rows per thread (2 packed f32x2 pairs)
#define TPB 128
#define MAXPART 8192

// ---------------- device scratch (no allocs allowed) ----------------
__device__ float  g_M1[DD*DD];   // M1[k][m] = sum_j W[j,k]*Wi[j,m]
__device__ float  g_c1[DD];      // c1[m]    = sum_j b[j]*Wi[j,m] + 1
__device__ float  g_Wt[DD*DD];   // Wt[m][n] = W[n,m]
__device__ double g_psum[MAXPART];
__device__ double g_pabs[MAXPART];

// ---------------- packed f32x2 helpers ----------------
__device__ __forceinline__ u64 fma2(u64 a, u64 b, u64 c) {
    u64 d;
    asm("fma.rn.f32x2 %0, %1, %2, %3;" : "=l"(d) : "l"(a), "l"(b), "l"(c));
    return d;
}
__device__ __forceinline__ u64 add2(u64 a, u64 b) {
    u64 d;
    asm("add.rn.f32x2 %0, %1, %2;" : "=l"(d) : "l"(a), "l"(b));
    return d;
}
__device__ __forceinline__ u64 pack2(float lo, float hi) {
    u64 d;
    asm("mov.b64 %0, {%1, %2};" : "=l"(d) : "f"(lo), "f"(hi));
    return d;
}
__device__ __forceinline__ float lo2(u64 v) { return __uint_as_float((unsigned)v); }
__device__ __forceinline__ float hi2(u64 v) { return __uint_as_float((unsigned)(v >> 32)); }
__device__ __forceinline__ u64 relu2(u64 v) {
    return pack2(fmaxf(lo2(v), 0.0f), fmaxf(hi2(v), 0.0f));
}

// ---------------- setup: fold first two matmuls, transpose W ----------------
__global__ void setup_kernel(const float* __restrict__ W,
                             const float* __restrict__ b,
                             const float* __restrict__ Wi) {
    __shared__ float sW[DD*DD], sWi[DD*DD];
    int t = threadIdx.x;
    if (t < DD*DD) { sW[t] = W[t]; sWi[t] = Wi[t]; }
    __syncthreads();
    if (t < DD*DD) {
        int k = t / DD, m = t % DD;
        float acc = 0.0f;
        #pragma unroll
        for (int j = 0; j < DD; j++)
            acc = fmaf(sW[j*DD + k], sWi[j*DD + m], acc);
        g_M1[t] = acc;
        g_Wt[t] = sW[m*DD + k];      // t=(m,n): Wt[m][n] = W[n][m]
    }
    if (t < DD) {
        float acc = 1.0f;
        #pragma unroll
        for (int j = 0; j < DD; j++)
            acc = fmaf(b[j], sWi[j*DD + t], acc);
        g_c1[t] = acc;
    }
}

// ---------------- main: 4 rows/thread, one group per thread, no loop --------
__global__ void __launch_bounds__(TPB, 2)
main_kernel(const float* __restrict__ X, const float* __restrict__ b,
            long long nrows) {
    // duplicated (w,w) 64-bit pairs; 16B-aligned so one LDS.128 = 2 weights
    __shared__ __align__(16) u64 sM1[DD*DD];
    __shared__ __align__(16) u64 sWt[DD*DD];
    __shared__ u64 sc1[DD];
    __shared__ u64 sb[DD];

    int t = threadIdx.x;
    for (int i = t; i < DD*DD; i += TPB) {
        float v = g_M1[i]; sM1[i] = pack2(v, v);
        float w = g_Wt[i]; sWt[i] = pack2(w, w);
    }
    if (t < DD) {
        float v = g_c1[t]; sc1[t] = pack2(v, v);
        float w = b[t];    sb[t]  = pack2(w, w);
    }
    __syncthreads();

    long long ngroups = nrows / RPT;
    long long gid = (long long)blockIdx.x * TPB + t;

    u64 psum = 0ull, pabs = 0ull;   // packed (0.0f, 0.0f)

    if (gid < ngroups) {
        const float4* p = (const float4*)(X + gid * (long long)(RPT * DD));

        // ---- matmul1, k-streamed: h = relu(X @ M1 + c1) ----
        // x chunks loaded and consumed per 4-k block; only h stays live.
        u64 h0[DD], h1[DD];
        #pragma unroll
        for (int m = 0; m < DD; m++) { h0[m] = sc1[m]; h1[m] = sc1[m]; }

        #pragma unroll
        for (int i = 0; i < 5; i++) {            // k = 4i .. 4i+3
            float4 a = p[i];                     // row 0
            float4 q = p[5 + i];                 // row 1
            float4 c = p[10 + i];                // row 2
            float4 d = p[15 + i];                // row 3
            u64 xk[4][2];
            xk[0][0] = pack2(a.x, q.x); xk[0][1] = pack2(c.x, d.x);
            xk[1][0] = pack2(a.y, q.y); xk[1][1] = pack2(c.y, d.y);
            xk[2][0] = pack2(a.z, q.z); xk[2][1] = pack2(c.z, d.z);
            xk[3][0] = pack2(a.w, q.w); xk[3][1] = pack2(c.w, d.w);
            #pragma unroll
            for (int kk = 0; kk < 4; kk++) {
                int k = 4*i + kk;
                #pragma unroll
                for (int m = 0; m < DD; m += 2) {
                    ulonglong2 w = *(const ulonglong2*)&sM1[k*DD + m];
                    h0[m]   = fma2(xk[kk][0], w.x, h0[m]);
                    h0[m+1] = fma2(xk[kk][0], w.y, h0[m+1]);
                    h1[m]   = fma2(xk[kk][1], w.x, h1[m]);
                    h1[m+1] = fma2(xk[kk][1], w.y, h1[m+1]);
                }
            }
        }
        #pragma unroll
        for (int m = 0; m < DD; m++) { h0[m] = relu2(h0[m]); h1[m] = relu2(h1[m]); }

        // ---- matmul2, n-blocked by 4: h3 = h @ W^T + b ----
        #pragma unroll
        for (int nb = 0; nb < 5; nb++) {
            const int n0 = nb * 4;
            u64 o00 = sb[n0],   o01 = sb[n0+1], o02 = sb[n0+2], o03 = sb[n0+3];
            u64 o10 = o00, o11 = o01, o12 = o02, o13 = o03;
            #pragma unroll
            for (int m = 0; m < DD; m++) {
                ulonglong2 wa = *(const ulonglong2*)&sWt[m*DD + n0];
                ulonglong2 wb = *(const ulonglong2*)&sWt[m*DD + n0 + 2];
                o00 = fma2(h0[m], wa.x, o00);
                o01 = fma2(h0[m], wa.y, o01);
                o02 = fma2(h0[m], wb.x, o02);
                o03 = fma2(h0[m], wb.y, o03);
                o10 = fma2(h1[m], wa.x, o10);
                o11 = fma2(h1[m], wa.y, o11);
                o12 = fma2(h1[m], wb.x, o12);
                o13 = fma2(h1[m], wb.y, o13);
            }
            const u64 MABS = 0x7FFFFFFF7FFFFFFFull;
            psum = add2(psum, add2(add2(o00, o10), add2(o01, o11)));
            psum = add2(psum, add2(add2(o02, o12), add2(o03, o13)));
            pabs = add2(pabs, add2(add2(o00 & MABS, o10 & MABS),
                                   add2(o01 & MABS, o11 & MABS)));
            pabs = add2(pabs, add2(add2(o02 & MABS, o12 & MABS),
                                   add2(o03 & MABS, o13 & MABS)));
        }
    }

    // ---- scalar tail (nrows % RPT), one thread handles it ----
    if (blockIdx.x == 0 && t == 0) {
        for (long long r = ngroups * RPT; r < nrows; r++) {
            float hs[DD];
            for (int m = 0; m < DD; m++) {
                float acc = lo2(sc1[m]);
                for (int k = 0; k < DD; k++)
                    acc = fmaf(X[r*DD + k], lo2(sM1[k*DD + m]), acc);
                hs[m] = fmaxf(acc, 0.0f);
            }
            for (int n = 0; n < DD; n++) {
                float acc = lo2(sb[n]);
                for (int m = 0; m < DD; m++)
                    acc = fmaf(hs[m], lo2(sWt[m*DD + n]), acc);
                psum = add2(psum, pack2(acc, 0.0f));
                pabs = add2(pabs, pack2(fabsf(acc), 0.0f));
            }
        }
    }

    // ---- reduce: warp shuffle -> shared -> per-block partial ----
    float ts = lo2(psum) + hi2(psum);
    float ta = lo2(pabs) + hi2(pabs);
    #pragma unroll
    for (int o = 16; o > 0; o >>= 1) {
        ts += __shfl_down_sync(0xFFFFFFFFu, ts, o);
        ta += __shfl_down_sync(0xFFFFFFFFu, ta, o);
    }
    __shared__ double rs[TPB/32], ra[TPB/32];
    if ((t & 31) == 0) { rs[t >> 5] = (double)ts; ra[t >> 5] = (double)ta; }
    __syncthreads();
    if (t == 0) {
        double S = 0.0, A = 0.0;
        #pragma unroll
        for (int i = 0; i < TPB/32; i++) { S += rs[i]; A += ra[i]; }
        g_psum[blockIdx.x] = S;
        g_pabs[blockIdx.x] = A;
    }
}

// ---------------- finalize: reduce partials, halving count, write scalar ----
__global__ void final_kernel(float* __restrict__ out, int nb) {
    __shared__ double ss[512], sa[512];
    int t = threadIdx.x;
    double S = 0.0, A = 0.0;
    for (int i = t; i < nb; i += 512) { S += g_psum[i]; A += g_pabs[i]; }
    ss[t] = S; sa[t] = A;
    __syncthreads();
    for (int o = 256; o > 0; o >>= 1) {
        if (t < o) { ss[t] += ss[t + o]; sa[t] += sa[t + o]; }
        __syncthreads();
    }
    if (t == 0) {
        float s = (float)sa[0];
        int k = 0;
        while (s > 1.0f && k < 300) { s *= 0.5f; k++; }
        out[0] = (float)ldexp(ss[0], -k);   // sum(h) * 2^-k, exact scale
    }
}

// ---------------- launch ----------------
extern "C" void kernel_launch(void* const* d_in, const int* in_sizes, int n_in,
                              void* d_out, int out_size) {
    const float* X  = (const float*)d_in[0];
    const float* W  = (const float*)d_in[1];
    const float* b  = (const float*)d_in[2];
    const float* Wi = (const float*)d_in[3];

    long long nrows   = (long long)in_sizes[0] / DD;
    long long ngroups = nrows / RPT;
    int nb = (int)((ngroups + TPB - 1) / TPB);
    if (nb < 1) nb = 1;
    if (nb > MAXPART) nb = MAXPART;   // not hit at B=1e6 (nb=1954)

    setup_kernel<<<1, 512>>>(W, b, Wi);
    main_kernel<<<nb, TPB>>>(X, b, nrows);
    final_kernel<<<1, 512>>>((float*)d_out, nb);
}

// round 5
// speedup vs baseline: 17.8364x; 1.8445x over previous
#include <cuda_runtime.h>
#include <stdint.h>
#include <math.h>

#define DD   20
#define TPB  128
#define WPB  4               // warps per block
#define NCTA 608             // 152 SMs x 4 CTAs
#define HST  24              // h smem row stride (floats)

__device__ double   g_psum[NCTA];
__device__ double   g_pabs[NCTA];
__device__ unsigned g_done = 0;

static __device__ __forceinline__ uint32_t f2tf(float f) {
    uint32_t u; asm("cvt.rna.tf32.f32 %0, %1;" : "=r"(u) : "f"(f)); return u;
}
static __device__ __forceinline__ void mma8(float* c, const uint32_t* a, const uint32_t* b) {
    asm volatile("mma.sync.aligned.m16n8k8.row.col.f32.tf32.tf32.f32 "
        "{%0,%1,%2,%3}, {%4,%5,%6,%7}, {%8,%9}, {%0,%1,%2,%3};"
        : "+f"(c[0]), "+f"(c[1]), "+f"(c[2]), "+f"(c[3])
        : "r"(a[0]), "r"(a[1]), "r"(a[2]), "r"(a[3]), "r"(b[0]), "r"(b[1]));
}

__global__ void __launch_bounds__(TPB)
fused_kernel(const float* __restrict__ X, const float* __restrict__ W,
             const float* __restrict__ bvec, const float* __restrict__ Wi,
             long long nrows, float* __restrict__ out) {
    __shared__ float  sW[400], sWi[400], sM1[400], sc1[DD], sb2[DD];
    __shared__ float  sh[WPB][2][16 * HST];    // per-warp, per-subtile h
    __shared__ double s_rs[WPB], s_ra[WPB];
    __shared__ double fs[TPB], fa[TPB];
    __shared__ int    s_last;

    const int t = threadIdx.x;
    const int wid = t >> 5, lane = t & 31;
    const int qr = lane >> 2, qc = lane & 3;   // groupID / threadID-in-group

    // ---- stage weights; precompute M1 = W^T @ Wi and c1 = b @ Wi + 1 ----
    for (int i = t; i < 400; i += TPB) { sW[i] = W[i]; sWi[i] = Wi[i]; }
    if (t < DD) sb2[t] = bvec[t];
    __syncthreads();
    for (int e = t; e < 400; e += TPB) {
        int k = e / 20, n = e % 20;
        float a = 0.f;
        #pragma unroll
        for (int j = 0; j < 20; j++) a = fmaf(sW[j*20 + k], sWi[j*20 + n], a);
        sM1[e] = a;
    }
    if (t < DD) {
        float a = 1.f;
        #pragma unroll
        for (int j = 0; j < 20; j++) a = fmaf(sb2[j], sWi[j*20 + t], a);
        sc1[t] = a;
    }
    __syncthreads();

    // ---- constant B fragments (tf32) + bias C-initializers, held in regs ----
    // B layout m16n8k8: b0 at (k=qc, n=qr), b1 at (k=qc+4, n=qr), per 8x8 chunk
    uint32_t b1f[3][3][2], b2f[3][3][2];
    float    bi1[3][2], bi2[3][2];
    #pragma unroll
    for (int j = 0; j < 3; j++) {
        int k0 = 8*j + qc, k1 = k0 + 4;
        #pragma unroll
        for (int i = 0; i < 3; i++) {
            int n = 8*i + qr;
            float v0 = (k0 < 20 && n < 20) ? sM1[k0*20 + n] : 0.f;
            float v1 = (k1 < 20 && n < 20) ? sM1[k1*20 + n] : 0.f;
            b1f[j][i][0] = f2tf(v0); b1f[j][i][1] = f2tf(v1);
            float w0 = (k0 < 20 && n < 20) ? sW[n*20 + k0] : 0.f;  // B2[k][n]=W[n][k]
            float w1 = (k1 < 20 && n < 20) ? sW[n*20 + k1] : 0.f;
            b2f[j][i][0] = f2tf(w0); b2f[j][i][1] = f2tf(w1);
        }
    }
    #pragma unroll
    for (int i = 0; i < 3; i++) {
        int n0 = 8*i + 2*qc;
        bi1[i][0] = (n0     < 20) ? sc1[n0]     : 0.f;
        bi1[i][1] = (n0 + 1 < 20) ? sc1[n0 + 1] : 0.f;
        bi2[i][0] = (n0     < 20) ? sb2[n0]     : 0.f;
        bi2[i][1] = (n0 + 1 < 20) ? sb2[n0 + 1] : 0.f;
    }

    // ---- mainloop: each warp owns 32-row tiles (two independent 16-row subtiles) ----
    const long long ntiles = (nrows + 31) >> 5;
    const long long gw = (long long)blockIdx.x * WPB + wid;
    const long long nw = (long long)gridDim.x * WPB;

    float accS = 0.f, accA = 0.f;

    for (long long tl = gw; tl < ntiles; tl += nw) {
        const long long Rt = tl << 5;

        // ---- load A fragments for both subtiles (20 LDG, high MLP) ----
        uint32_t a[2][3][4];
        #pragma unroll
        for (int s = 0; s < 2; s++) {
            long long r0 = Rt + s*16 + qr;      if (r0 > nrows - 1) r0 = nrows - 1;
            long long r1 = Rt + s*16 + qr + 8;  if (r1 > nrows - 1) r1 = nrows - 1;
            const float* p0 = X + r0 * DD;
            const float* p1 = X + r1 * DD;
            #pragma unroll
            for (int j = 0; j < 2; j++) {
                a[s][j][0] = f2tf(p0[8*j + qc]);
                a[s][j][1] = f2tf(p1[8*j + qc]);
                a[s][j][2] = f2tf(p0[8*j + qc + 4]);
                a[s][j][3] = f2tf(p1[8*j + qc + 4]);
            }
            a[s][2][0] = f2tf(p0[16 + qc]);
            a[s][2][1] = f2tf(p1[16 + qc]);
            a[s][2][2] = 0u;   // K-pad cols 20-23
            a[s][2][3] = 0u;
        }

        // ---- stage 1: h = relu(X @ M1 + c1), store to per-warp smem ----
        #pragma unroll
        for (int s = 0; s < 2; s++) {
            float* hw = sh[wid][s];
            #pragma unroll
            for (int i = 0; i < 3; i++) {
                float c[4] = { bi1[i][0], bi1[i][1], bi1[i][0], bi1[i][1] };
                mma8(c, a[s][0], b1f[0][i]);
                mma8(c, a[s][1], b1f[1][i]);
                mma8(c, a[s][2], b1f[2][i]);
                int col = 8*i + 2*qc;
                float2 v0 = make_float2(fmaxf(c[0], 0.f), fmaxf(c[1], 0.f));
                float2 v1 = make_float2(fmaxf(c[2], 0.f), fmaxf(c[3], 0.f));
                *(float2*)&hw[qr*HST + col]       = v0;
                *(float2*)&hw[(qr + 8)*HST + col] = v1;
            }
        }
        __syncwarp();

        // ---- layout conversion: reload h as A fragments ----
        uint32_t a2[2][3][4];
        #pragma unroll
        for (int s = 0; s < 2; s++) {
            const float* hw = sh[wid][s];
            #pragma unroll
            for (int j = 0; j < 3; j++) {
                a2[s][j][0] = f2tf(hw[qr*HST + 8*j + qc]);
                a2[s][j][1] = f2tf(hw[(qr + 8)*HST + 8*j + qc]);
                a2[s][j][2] = f2tf(hw[qr*HST + 8*j + qc + 4]);
                a2[s][j][3] = f2tf(hw[(qr + 8)*HST + 8*j + qc + 4]);
            }
        }
        __syncwarp();   // reads done before next iteration's stores

        // ---- stage 2: h3 = h @ W^T + b, accumulate sum / abs-sum ----
        #pragma unroll
        for (int s = 0; s < 2; s++) {
            bool v0ok = (Rt + s*16 + qr)     < nrows;
            bool v1ok = (Rt + s*16 + qr + 8) < nrows;
            #pragma unroll
            for (int i = 0; i < 3; i++) {
                float c[4] = { bi2[i][0], bi2[i][1], bi2[i][0], bi2[i][1] };
                mma8(c, a2[s][0], b2f[0][i]);
                mma8(c, a2[s][1], b2f[1][i]);
                mma8(c, a2[s][2], b2f[2][i]);
                // cols >= 20 are exactly 0 (zero B frags + zero bias) — safe to add
                if (v0ok) { accS += c[0] + c[1]; accA += fabsf(c[0]) + fabsf(c[1]); }
                if (v1ok) { accS += c[2] + c[3]; accA += fabsf(c[2]) + fabsf(c[3]); }
            }
        }
    }

    // ---- CTA reduce ----
    #pragma unroll
    for (int o = 16; o > 0; o >>= 1) {
        accS += __shfl_down_sync(0xFFFFFFFFu, accS, o);
        accA += __shfl_down_sync(0xFFFFFFFFu, accA, o);
    }
    if (lane == 0) { s_rs[wid] = (double)accS; s_ra[wid] = (double)accA; }
    __syncthreads();

    if (t == 0) {
        double S = s_rs[0] + s_rs[1] + s_rs[2] + s_rs[3];
        double A = s_ra[0] + s_ra[1] + s_ra[2] + s_ra[3];
        g_psum[blockIdx.x] = S;
        g_pabs[blockIdx.x] = A;
        __threadfence();
        unsigned v = atomicAdd(&g_done, 1u);
        s_last = (v == gridDim.x - 1) ? 1 : 0;
    }
    __syncthreads();

    // ---- last CTA: global reduce + exact halving count + write scalar ----
    if (s_last) {
        __threadfence();
        double S = 0.0, A = 0.0;
        for (int i = t; i < (int)gridDim.x; i += TPB) { S += g_psum[i]; A += g_pabs[i]; }
        fs[t] = S; fa[t] = A;
        __syncthreads();
        for (int o = TPB/2; o > 0; o >>= 1) {
            if (t < o) { fs[t] += fs[t + o]; fa[t] += fa[t + o]; }
            __syncthreads();
        }
        if (t == 0) {
            float s = (float)fa[0];
            int k = 0;
            while (s > 1.0f && k < 300) { s *= 0.5f; k++; }
            out[0] = (float)ldexp(fs[0], -k);   // sum(h) * 2^-k (exact scale)
            __threadfence();
            g_done = 0;                          // reset for next graph replay
        }
    }
}

// ---------------- launch ----------------
extern "C" void kernel_launch(void* const* d_in, const int* in_sizes, int n_in,
                              void* d_out, int out_size) {
    const float* X  = (const float*)d_in[0];
    const float* W  = (const float*)d_in[1];
    const float* b  = (const float*)d_in[2];
    const float* Wi = (const float*)d_in[3];

    long long nrows = (long long)in_sizes[0] / DD;

    fused_kernel<<<NCTA, TPB>>>(X, W, b, Wi, nrows, (float*)d_out);
}

// round 6
// speedup vs baseline: 19.2656x; 1.0801x over previous
#include <cuda_runtime.h>
#include <stdint.h>
#include <math.h>

#define DD   20
#define TPB  128
#define WPB  4               // warps per block
#define NCTA 608             // 152 SMs x 4 CTAs
#define HST  24              // h smem row stride (floats)

__device__ double   g_psum[NCTA];
__device__ double   g_pabs[NCTA];
__device__ unsigned g_done = 0;

static __device__ __forceinline__ uint32_t f2tf(float f) {
    uint32_t u; asm("cvt.rna.tf32.f32 %0, %1;" : "=r"(u) : "f"(f)); return u;
}
static __device__ __forceinline__ void mma8(float* c, const uint32_t* a, const uint32_t* b) {
    asm volatile("mma.sync.aligned.m16n8k8.row.col.f32.tf32.tf32.f32 "
        "{%0,%1,%2,%3}, {%4,%5,%6,%7}, {%8,%9}, {%0,%1,%2,%3};"
        : "+f"(c[0]), "+f"(c[1]), "+f"(c[2]), "+f"(c[3])
        : "r"(a[0]), "r"(a[1]), "r"(a[2]), "r"(a[3]), "r"(b[0]), "r"(b[1]));
}
static __device__ __forceinline__ uint32_t s2u(const void* p) {
    uint32_t a;
    asm("{ .reg .u64 t; cvta.to.shared.u64 t, %1; cvt.u32.u64 %0, t; }" : "=r"(a) : "l"(p));
    return a;
}
// per-warp tile prefetch: 2560B = 5 coalesced 16B cp.async per lane
static __device__ __forceinline__ void issue_tile(const char* Xb, long long tile,
                                                  long long ntiles, long long maxoff,
                                                  uint32_t dst, int lane) {
    if (tile >= ntiles) tile = ntiles - 1;
    long long base = tile * 2560 + (long long)lane * 16;
    #pragma unroll
    for (int c = 0; c < 5; c++) {
        long long off = base + c * 512;
        if (off > maxoff) off = maxoff;
        asm volatile("cp.async.cg.shared.global [%0], [%1], 16;"
                     :: "r"(dst + c * 512 + lane * 16), "l"(Xb + off) : "memory");
    }
    asm volatile("cp.async.commit_group;" ::: "memory");
}

__global__ void __launch_bounds__(TPB, 4)
fused_kernel(const float* __restrict__ X, const float* __restrict__ W,
             const float* __restrict__ bvec, const float* __restrict__ Wi,
             long long nrows, float* __restrict__ out) {
    __shared__ float  sW[400], sWi[400], sM1[400], sc1[DD], sb2[DD];
    __shared__ float  sh[WPB][2][16 * HST];          // per-warp h roundtrip
    __shared__ __align__(16) float sX[WPB][2][32 * DD];  // per-warp X double buffer
    __shared__ double s_rs[WPB], s_ra[WPB];
    __shared__ double fs[TPB], fa[TPB];
    __shared__ int    s_last;

    const int t = threadIdx.x;
    const int wid = t >> 5, lane = t & 31;
    const int qr = lane >> 2, qc = lane & 3;

    // ---- stage weights; precompute M1 = W^T @ Wi and c1 = b @ Wi + 1 ----
    for (int i = t; i < 400; i += TPB) { sW[i] = W[i]; sWi[i] = Wi[i]; }
    if (t < DD) sb2[t] = bvec[t];
    __syncthreads();
    for (int e = t; e < 400; e += TPB) {
        int k = e / 20, n = e % 20;
        float a = 0.f;
        #pragma unroll
        for (int j = 0; j < 20; j++) a = fmaf(sW[j*20 + k], sWi[j*20 + n], a);
        sM1[e] = a;
    }
    if (t < DD) {
        float a = 1.f;
        #pragma unroll
        for (int j = 0; j < 20; j++) a = fmaf(sb2[j], sWi[j*20 + t], a);
        sc1[t] = a;
    }
    __syncthreads();

    // ---- constant B fragments (tf32) + bias C-initializers, in regs ----
    uint32_t b1f[3][3][2], b2f[3][3][2];
    float    bi1[3][2], bi2[3][2];
    #pragma unroll
    for (int j = 0; j < 3; j++) {
        int k0 = 8*j + qc, k1 = k0 + 4;
        #pragma unroll
        for (int i = 0; i < 3; i++) {
            int n = 8*i + qr;
            float v0 = (k0 < 20 && n < 20) ? sM1[k0*20 + n] : 0.f;
            float v1 = (k1 < 20 && n < 20) ? sM1[k1*20 + n] : 0.f;
            b1f[j][i][0] = f2tf(v0); b1f[j][i][1] = f2tf(v1);
            float w0 = (k0 < 20 && n < 20) ? sW[n*20 + k0] : 0.f;
            float w1 = (k1 < 20 && n < 20) ? sW[n*20 + k1] : 0.f;
            b2f[j][i][0] = f2tf(w0); b2f[j][i][1] = f2tf(w1);
        }
    }
    #pragma unroll
    for (int i = 0; i < 3; i++) {
        int n0 = 8*i + 2*qc;
        bi1[i][0] = (n0     < 20) ? sc1[n0]     : 0.f;
        bi1[i][1] = (n0 + 1 < 20) ? sc1[n0 + 1] : 0.f;
        bi2[i][0] = (n0     < 20) ? sb2[n0]     : 0.f;
        bi2[i][1] = (n0 + 1 < 20) ? sb2[n0 + 1] : 0.f;
    }

    // ---- mainloop: 32 rows/warp/iter, cp.async double-buffered ----
    const long long ntiles = (nrows + 31) >> 5;
    const long long gw = (long long)blockIdx.x * WPB + wid;
    const long long nw = (long long)gridDim.x * WPB;
    const long long maxoff = nrows * 80 - 16;
    const char* Xb = (const char*)X;
    const uint32_t xs0 = s2u(&sX[wid][0][0]);
    const uint32_t xs1 = s2u(&sX[wid][1][0]);

    float accS = 0.f, accA = 0.f;
    int p = 0;

    if (gw < ntiles) issue_tile(Xb, gw, ntiles, maxoff, xs0, lane);

    for (long long tl = gw; tl < ntiles; tl += nw) {
        issue_tile(Xb, tl + nw, ntiles, maxoff, p ? xs0 : xs1, lane);
        asm volatile("cp.async.wait_group 1;" ::: "memory");
        __syncwarp();

        const float* xs = &sX[wid][p][0];
        const long long Rt = tl << 5;

        // ---- A fragments from staged smem (conflict-free LDS) ----
        uint32_t a[2][3][4];
        #pragma unroll
        for (int s = 0; s < 2; s++) {
            const float* q0 = xs + (s*16 + qr) * 20;
            const float* q1 = q0 + 8 * 20;
            #pragma unroll
            for (int j = 0; j < 2; j++) {
                a[s][j][0] = f2tf(q0[8*j + qc]);
                a[s][j][1] = f2tf(q1[8*j + qc]);
                a[s][j][2] = f2tf(q0[8*j + qc + 4]);
                a[s][j][3] = f2tf(q1[8*j + qc + 4]);
            }
            a[s][2][0] = f2tf(q0[16 + qc]);
            a[s][2][1] = f2tf(q1[16 + qc]);
            a[s][2][2] = 0u;
            a[s][2][3] = 0u;
        }

        // ---- stage 1: h = relu(X @ M1 + c1) -> per-warp smem ----
        #pragma unroll
        for (int s = 0; s < 2; s++) {
            float* hw = sh[wid][s];
            #pragma unroll
            for (int i = 0; i < 3; i++) {
                float c[4] = { bi1[i][0], bi1[i][1], bi1[i][0], bi1[i][1] };
                mma8(c, a[s][0], b1f[0][i]);
                mma8(c, a[s][1], b1f[1][i]);
                mma8(c, a[s][2], b1f[2][i]);
                int col = 8*i + 2*qc;
                float2 v0 = make_float2(fmaxf(c[0], 0.f), fmaxf(c[1], 0.f));
                float2 v1 = make_float2(fmaxf(c[2], 0.f), fmaxf(c[3], 0.f));
                *(float2*)&hw[qr*HST + col]       = v0;
                *(float2*)&hw[(qr + 8)*HST + col] = v1;
            }
        }
        __syncwarp();

        // ---- layout conversion: h -> A fragments ----
        uint32_t a2[2][3][4];
        #pragma unroll
        for (int s = 0; s < 2; s++) {
            const float* hw = sh[wid][s];
            #pragma unroll
            for (int j = 0; j < 3; j++) {
                a2[s][j][0] = f2tf(hw[qr*HST + 8*j + qc]);
                a2[s][j][1] = f2tf(hw[(qr + 8)*HST + 8*j + qc]);
                a2[s][j][2] = f2tf(hw[qr*HST + 8*j + qc + 4]);
                a2[s][j][3] = f2tf(hw[(qr + 8)*HST + 8*j + qc + 4]);
            }
        }
        __syncwarp();

        // ---- stage 2: h3 = h @ W^T + b, accumulate ----
        #pragma unroll
        for (int s = 0; s < 2; s++) {
            bool v0ok = (Rt + s*16 + qr)     < nrows;
            bool v1ok = (Rt + s*16 + qr + 8) < nrows;
            #pragma unroll
            for (int i = 0; i < 3; i++) {
                float c[4] = { bi2[i][0], bi2[i][1], bi2[i][0], bi2[i][1] };
                mma8(c, a2[s][0], b2f[0][i]);
                mma8(c, a2[s][1], b2f[1][i]);
                mma8(c, a2[s][2], b2f[2][i]);
                if (v0ok) { accS += c[0] + c[1]; accA += fabsf(c[0]) + fabsf(c[1]); }
                if (v1ok) { accS += c[2] + c[3]; accA += fabsf(c[2]) + fabsf(c[3]); }
            }
        }
        p ^= 1;
    }
    asm volatile("cp.async.wait_group 0;" ::: "memory");   // drain tail prefetch

    // ---- CTA reduce ----
    #pragma unroll
    for (int o = 16; o > 0; o >>= 1) {
        accS += __shfl_down_sync(0xFFFFFFFFu, accS, o);
        accA += __shfl_down_sync(0xFFFFFFFFu, accA, o);
    }
    if (lane == 0) { s_rs[wid] = (double)accS; s_ra[wid] = (double)accA; }
    __syncthreads();

    if (t == 0) {
        double S = s_rs[0] + s_rs[1] + s_rs[2] + s_rs[3];
        double A = s_ra[0] + s_ra[1] + s_ra[2] + s_ra[3];
        g_psum[blockIdx.x] = S;
        g_pabs[blockIdx.x] = A;
        __threadfence();
        unsigned v = atomicAdd(&g_done, 1u);
        s_last = (v == gridDim.x - 1) ? 1 : 0;
    }
    __syncthreads();

    // ---- last CTA: global reduce + exact halving count + write scalar ----
    if (s_last) {
        __threadfence();
        double S = 0.0, A = 0.0;
        for (int i = t; i < (int)gridDim.x; i += TPB) { S += g_psum[i]; A += g_pabs[i]; }
        fs[t] = S; fa[t] = A;
        __syncthreads();
        for (int o = TPB/2; o > 0; o >>= 1) {
            if (t < o) { fs[t] += fs[t + o]; fa[t] += fa[t + o]; }
            __syncthreads();
        }
        if (t == 0) {
            float s = (float)fa[0];
            int k = 0;
            while (s > 1.0f && k < 300) { s *= 0.5f; k++; }
            out[0] = (float)ldexp(fs[0], -k);   // sum(h) * 2^-k (exact scale)
            __threadfence();
            g_done = 0;                          // reset for next graph replay
        }
    }
}

// ---------------- launch ----------------
extern "C" void kernel_launch(void* const* d_in, const int* in_sizes, int n_in,
                              void* d_out, int out_size) {
    const float* X  = (const float*)d_in[0];
    const float* W  = (const float*)d_in[1];
    const float* b  = (const float*)d_in[2];
    const float* Wi = (const float*)d_in[3];

    long long nrows = (long long)in_sizes[0] / DD;

    fused_kernel<<<NCTA, TPB>>>(X, W, b, Wi, nrows, (float*)d_out);
}